// round 16
// baseline (speedup 1.0000x reference)
#include <cuda_runtime.h>
#include <cuda_bf16.h>
#include <math.h>

// ContrastiveLoss: N=8192 points, D=64, labels int32 in [0,8).
// loss = [ sum_{same-label,i!=j} d2  +  sum_{diff-label} max(1-d,0)^2 ] / (N*(N-1))
//
//   pos term: exact closed form per class: sum d2 = 2*(n_c*S2_c - |S1_c|^2)  (O(N*D))
//   neg term: nonzero only when d < 1. Screen all pairs on the first 8 dims with
//             tf32 tensor-core MMA (m16n8k8): tiles are tf32-rounded ONCE, norms are
//             computed from the SAME rounded values, so the screen tests the exact
//             distance of the rounded vectors; threshold d2 < 1.10 absorbs the
//             rounding delta (<0.03) vs the true d2 < 1.01 bound. Survivors are
//             compacted to smem and exactly evaluated in fp32/fp64 on all 64 dims.
// ONE kernel: blocks [0,NSCR) screen, [NSCR,NBLK) pos-term prep; last block
// (atomic ticket) reduces and writes the loss, then resets accumulators.

#define N_PTS 8192
#define NDIM  64
#define NCLS  8
#define TT    128     // screen tile: 128 x 128 pairs
#define SCAP  2048    // survivor buffer entries per block
#define NSCR  2080    // screen blocks: 64*65/2 (tile-triangular, bj >= bi)
#define NPREP 512     // prep blocks (16 rows each)
#define NBLK  (NSCR + NPREP)
#define MARG  0.55f   // pass <=> dot - hi - hj + MARG > 0  <=> rounded d2_8 < 1.10

__device__ float  g_s1[NCLS * NDIM];
__device__ float  g_s2[NCLS * NDIM];
__device__ int    g_hist[NCLS];
__device__ double g_neg;
__device__ int    g_done;

// ---------------- rare path: exact 64-dim evaluation ----------------
__device__ __noinline__ void eval_pair(const float* __restrict__ X,
                                       const int* __restrict__ lab, int i, int j) {
    if (j <= i) return;                 // self pairs / duplicates from diag tiles
    if (lab[i] == lab[j]) return;       // same-label handled in closed form
    const float4* xi = (const float4*)(X + i * NDIM);
    const float4* xj = (const float4*)(X + j * NDIM);
    float s = 0.0f;
#pragma unroll
    for (int q = 0; q < 16; q++) {
        float4 a = xi[q], b = xj[q];
        float d;
        d = a.x - b.x; s = fmaf(d, d, s);
        d = a.y - b.y; s = fmaf(d, d, s);
        d = a.z - b.z; s = fmaf(d, d, s);
        d = a.w - b.w; s = fmaf(d, d, s);
    }
    if (s < 1.0f) {
        float u = 1.0f - sqrtf(fmaxf(s, 0.0f));
        atomicAdd(&g_neg, 2.0 * (double)u * (double)u);   // unordered -> ordered
    }
}

__device__ __forceinline__ float to_tf32(float f) {
    unsigned u;
    asm("cvt.rna.tf32.f32 %0, %1;" : "=r"(u) : "f"(f));
    return __uint_as_float(u);
}

struct SmemScreen {
    float    A[TT * 9];      // i-tile, tf32-rounded, row stride 9 (bank-conflict-free)
    float    B[TT * 9];      // j-tile
    float    hi[TT];         // 0.5*|row|^2 of rounded values
    float    hj[TT];
    unsigned sbuf[SCAP];
    int      scnt;
};
struct SmemPrep {
    int   slab[16];
    float red1[2][NCLS * NDIM];
    float red2[2][NCLS * NDIM];
};
union SmemU { SmemScreen scr; SmemPrep prep; };

// ---------------- the one kernel ----------------------------------------------
__global__ void __launch_bounds__(128) fused_kernel(const float* __restrict__ X,
                                                    const int* __restrict__ lab,
                                                    float* __restrict__ out) {
    __shared__ __align__(16) SmemU sm;
    __shared__ int    s_last;
    __shared__ double s_part[4];
    int t = threadIdx.x;
    const float4* Xv = (const float4*)X;

    if (blockIdx.x >= NSCR) {
        // ---------------- prep path: rows [pb*16, pb*16+16) ----------------
        SmemPrep& sp = sm.prep;
        int pb = blockIdx.x - NSCR;
        int k  = t & 63;
        int g  = t >> 6;
        int r0 = pb * 16 + g * 8;
        if (t < 16) sp.slab[t] = lab[pb * 16 + t];
        __syncthreads();

        float a1[NCLS], a2[NCLS];
#pragma unroll
        for (int c = 0; c < NCLS; c++) { a1[c] = 0.0f; a2[c] = 0.0f; }
#pragma unroll
        for (int rr = 0; rr < 8; ++rr) {
            float v  = X[(r0 + rr) * NDIM + k];
            float v2 = v * v;
            int   c  = sp.slab[g * 8 + rr];
#pragma unroll
            for (int cc = 0; cc < NCLS; cc++) {
                bool m = (cc == c);
                a1[cc] += m ? v  : 0.0f;
                a2[cc] += m ? v2 : 0.0f;
            }
        }
#pragma unroll
        for (int cc = 0; cc < NCLS; cc++) {
            sp.red1[g][cc * NDIM + k] = a1[cc];
            sp.red2[g][cc * NDIM + k] = a2[cc];
        }
        __syncthreads();
#pragma unroll
        for (int q = 0; q < 4; q++) {
            int idx = q * 128 + t;
            atomicAdd(&g_s1[idx], sp.red1[0][idx] + sp.red1[1][idx]);
            atomicAdd(&g_s2[idx], sp.red2[0][idx] + sp.red2[1][idx]);
        }
        if (t < NCLS) {
            int cnt = 0;
#pragma unroll
            for (int rr = 0; rr < 16; rr++) cnt += (sp.slab[rr] == t) ? 1 : 0;
            atomicAdd(&g_hist[t], cnt);
        }
    } else {
        // ---------------- screen path (tf32 MMA) ----------------
        SmemScreen& ss = sm.scr;
        // decode linear id -> (bi, bj), bj >= bi; counts per bi: 64 - bi
        int L = blockIdx.x;
        int bi = 0;
#pragma unroll
        for (int k = 0; k < 64; k++) {
            int cnt = 64 - k;
            bool adv = (L >= cnt);
            L  -= adv ? cnt : 0;
            bi += adv ? 1 : 0;
        }
        int bj    = bi + L;
        int ibase = bi * TT;
        int jbase = bj * TT;

        if (t == 0) ss.scnt = 0;
        // thread t loads i-row ibase+t and j-row jbase+t (first 8 dims), tf32-rounds,
        // stores to smem (stride 9) and computes half-norms of the rounded values.
        {
            float4 f0 = Xv[(ibase + t) * 16 + 0];
            float4 f1 = Xv[(ibase + t) * 16 + 1];
            float v[8] = {f0.x, f0.y, f0.z, f0.w, f1.x, f1.y, f1.z, f1.w};
            float hn = 0.0f;
#pragma unroll
            for (int d = 0; d < 8; d++) {
                float fr = to_tf32(v[d]);
                ss.A[t * 9 + d] = fr;
                hn = fmaf(fr, fr, hn);
            }
            ss.hi[t] = 0.5f * hn;
        }
        {
            float4 f0 = Xv[(jbase + t) * 16 + 0];
            float4 f1 = Xv[(jbase + t) * 16 + 1];
            float v[8] = {f0.x, f0.y, f0.z, f0.w, f1.x, f1.y, f1.z, f1.w};
            float hn = 0.0f;
#pragma unroll
            for (int d = 0; d < 8; d++) {
                float fr = to_tf32(v[d]);
                ss.B[t * 9 + d] = fr;
                hn = fmaf(fr, fr, hn);
            }
            ss.hj[t] = 0.5f * hn;
        }
        __syncthreads();

        int w    = t >> 5;
        int lane = t & 31;
        int g    = lane >> 2;       // 0..7
        int q    = lane & 3;        // 0..3

        // warp w owns i-subtiles {2w, 2w+1} (m16 each) x 16 j-subtiles (n8 each)
#pragma unroll
        for (int s = 0; s < 2; ++s) {
            int mi = w * 2 + s;
            int r0 = mi * 16 + g;           // local row of c0/c1
            int r1 = r0 + 8;                // local row of c2/c3
            unsigned a0 = __float_as_uint(ss.A[r0 * 9 + q]);
            unsigned a1 = __float_as_uint(ss.A[r1 * 9 + q]);
            unsigned a2 = __float_as_uint(ss.A[r0 * 9 + q + 4]);
            unsigned a3 = __float_as_uint(ss.A[r1 * 9 + q + 4]);
            float ci0 = MARG - ss.hi[r0];
            float ci1 = MARG - ss.hi[r1];
            int row0 = ibase + r0;
            int row1 = ibase + r1;
#pragma unroll
            for (int nj = 0; nj < 16; ++nj) {
                unsigned b0 = __float_as_uint(ss.B[(nj * 8 + g) * 9 + q]);
                unsigned b1 = __float_as_uint(ss.B[(nj * 8 + g) * 9 + q + 4]);
                float hj0 = ss.hj[nj * 8 + 2 * q];
                float hj1 = ss.hj[nj * 8 + 2 * q + 1];
                float c0 = ci0 - hj0, c1 = ci0 - hj1;
                float c2 = ci1 - hj0, c3 = ci1 - hj1;
                asm volatile(
                    "mma.sync.aligned.m16n8k8.row.col.f32.tf32.tf32.f32 "
                    "{%0,%1,%2,%3}, {%4,%5,%6,%7}, {%8,%9}, {%0,%1,%2,%3};"
                    : "+f"(c0), "+f"(c1), "+f"(c2), "+f"(c3)
                    : "r"(a0), "r"(a1), "r"(a2), "r"(a3), "r"(b0), "r"(b1));
                bool p = (c0 > 0.0f) | (c1 > 0.0f) | (c2 > 0.0f) | (c3 > 0.0f);
                if (__any_sync(0xFFFFFFFFu, p)) {
                    int col0 = jbase + nj * 8 + 2 * q;
                    if (c0 > 0.0f) {
                        int ix = atomicAdd(&ss.scnt, 1);
                        if (ix < SCAP) ss.sbuf[ix] = ((unsigned)row0 << 13) | (unsigned)col0;
                    }
                    if (c1 > 0.0f) {
                        int ix = atomicAdd(&ss.scnt, 1);
                        if (ix < SCAP) ss.sbuf[ix] = ((unsigned)row0 << 13) | (unsigned)(col0 + 1);
                    }
                    if (c2 > 0.0f) {
                        int ix = atomicAdd(&ss.scnt, 1);
                        if (ix < SCAP) ss.sbuf[ix] = ((unsigned)row1 << 13) | (unsigned)col0;
                    }
                    if (c3 > 0.0f) {
                        int ix = atomicAdd(&ss.scnt, 1);
                        if (ix < SCAP) ss.sbuf[ix] = ((unsigned)row1 << 13) | (unsigned)(col0 + 1);
                    }
                }
            }
        }
        __syncthreads();

        if (ss.scnt <= SCAP) {
            int n = ss.scnt;
            for (int qq = t; qq < n; qq += 128) {
                unsigned e = ss.sbuf[qq];
                eval_pair(X, lab, (int)(e >> 13), (int)(e & 8191u));
            }
        } else {
            // overflow (correctness guard): scalar re-screen of this tile from smem
            // (rounded values; same lower-bound test), direct exact evaluation.
#pragma unroll 1
            for (int j = 0; j < TT; ++j) {
                float dot = 0.0f;
#pragma unroll
                for (int d = 0; d < 8; d++)
                    dot = fmaf(ss.A[t * 9 + d], ss.B[j * 9 + d], dot);
                if (dot > ss.hi[t] + ss.hj[j] - MARG)
                    eval_pair(X, lab, ibase + t, jbase + j);
            }
        }
    }

    // ---------------- completion ticket; last block finalizes ----------------
    __threadfence();
    __syncthreads();
    if (t == 0) {
        int v = atomicAdd(&g_done, 1);
        s_last = (v == NBLK - 1) ? 1 : 0;
    }
    __syncthreads();
    if (!s_last) return;

    double part = 0.0;
#pragma unroll
    for (int q = 0; q < 4; q++) {
        int idx = q * 128 + t;
        double S1 = (double)g_s1[idx];
        double S2 = (double)g_s2[idx];
        part += (double)g_hist[idx >> 6] * S2 - S1 * S1;
    }
#pragma unroll
    for (int s = 16; s > 0; s >>= 1)
        part += __shfl_down_sync(0xFFFFFFFFu, part, s);
    if ((t & 31) == 0) s_part[t >> 5] = part;
    __syncthreads();
    if (t == 0) {
        double pos  = 2.0 * (s_part[0] + s_part[1] + s_part[2] + s_part[3]);
        double loss = (pos + g_neg) / ((double)N_PTS * (double)(N_PTS - 1));
        out[0] = (float)loss;
    }
#pragma unroll
    for (int q = 0; q < 4; q++) {
        int idx = q * 128 + t;
        g_s1[idx] = 0.0f;
        g_s2[idx] = 0.0f;
    }
    if (t < NCLS) g_hist[t] = 0;
    if (t == 0) { g_neg = 0.0; g_done = 0; }
}

extern "C" void kernel_launch(void* const* d_in, const int* in_sizes, int n_in,
                              void* d_out, int out_size) {
    const float* X   = (const float*)d_in[0];
    const int*   lab = (const int*)d_in[1];
    float*       out = (float*)d_out;

    fused_kernel<<<NBLK, 128>>>(X, lab, out);
}

// round 17
// speedup vs baseline: 1.2360x; 1.2360x over previous
#include <cuda_runtime.h>
#include <cuda_bf16.h>
#include <math.h>

// ContrastiveLoss: N=8192 points, D=64, labels int32 in [0,8).
// loss = [ sum_{same-label,i!=j} d2  +  sum_{diff-label} max(1-d,0)^2 ] / (N*(N-1))
//
//   pos term: exact closed form per class: sum d2 = 2*(n_c*S2_c - |S1_c|^2)  (O(N*D))
//   neg term: nonzero only when d < 1. Screen all pairs on the first 8 dims with
//             tf32 tensor-core MMA (m16n8k8): tiles are tf32-rounded ONCE, norms
//             computed from the SAME rounded values, so the screen tests the exact
//             distance of the rounded vectors; threshold d2 < 1.10 absorbs the
//             rounding delta (<0.03) vs the true d2 < 1.01 bound. Survivors are
//             compacted to smem and exactly evaluated in fp32/fp64 on all 64 dims.
// ONE kernel: blocks [0,NSCR) screen, [NSCR,NBLK) pos-term prep; last block
// (atomic ticket) reduces and writes the loss, then resets accumulators.
// R17: __launch_bounds__(128,8) + partial nj unroll to fix R16's 145-reg /
// 18.5%-occupancy collapse.

#define N_PTS 8192
#define NDIM  64
#define NCLS  8
#define TT    128     // screen tile: 128 x 128 pairs
#define SCAP  2048    // survivor buffer entries per block
#define NSCR  2080    // screen blocks: 64*65/2 (tile-triangular, bj >= bi)
#define NPREP 512     // prep blocks (16 rows each)
#define NBLK  (NSCR + NPREP)
#define MARG  0.55f   // pass <=> dot - hi - hj + MARG > 0  <=> rounded d2_8 < 1.10

__device__ float  g_s1[NCLS * NDIM];
__device__ float  g_s2[NCLS * NDIM];
__device__ int    g_hist[NCLS];
__device__ double g_neg;
__device__ int    g_done;

// ---------------- rare path: exact 64-dim evaluation ----------------
__device__ __noinline__ void eval_pair(const float* __restrict__ X,
                                       const int* __restrict__ lab, int i, int j) {
    if (j <= i) return;                 // self pairs / duplicates from diag tiles
    if (lab[i] == lab[j]) return;       // same-label handled in closed form
    const float4* xi = (const float4*)(X + i * NDIM);
    const float4* xj = (const float4*)(X + j * NDIM);
    float s = 0.0f;
#pragma unroll
    for (int q = 0; q < 16; q++) {
        float4 a = xi[q], b = xj[q];
        float d;
        d = a.x - b.x; s = fmaf(d, d, s);
        d = a.y - b.y; s = fmaf(d, d, s);
        d = a.z - b.z; s = fmaf(d, d, s);
        d = a.w - b.w; s = fmaf(d, d, s);
    }
    if (s < 1.0f) {
        float u = 1.0f - sqrtf(fmaxf(s, 0.0f));
        atomicAdd(&g_neg, 2.0 * (double)u * (double)u);   // unordered -> ordered
    }
}

__device__ __forceinline__ float to_tf32(float f) {
    unsigned u;
    asm("cvt.rna.tf32.f32 %0, %1;" : "=r"(u) : "f"(f));
    return __uint_as_float(u);
}

struct SmemScreen {
    float    A[TT * 9];      // i-tile, tf32-rounded, row stride 9 (conflict-free)
    float    B[TT * 9];      // j-tile
    float    hi[TT];         // 0.5*|row|^2 of rounded values
    float    hj[TT];
    unsigned sbuf[SCAP];
    int      scnt;
};
struct SmemPrep {
    int   slab[16];
    float red1[2][NCLS * NDIM];
    float red2[2][NCLS * NDIM];
};
union SmemU { SmemScreen scr; SmemPrep prep; };

// ---------------- the one kernel ----------------------------------------------
__global__ void __launch_bounds__(128, 8) fused_kernel(const float* __restrict__ X,
                                                       const int* __restrict__ lab,
                                                       float* __restrict__ out) {
    __shared__ __align__(16) SmemU sm;
    __shared__ int    s_last;
    __shared__ double s_part[4];
    int t = threadIdx.x;
    const float4* Xv = (const float4*)X;

    if (blockIdx.x >= NSCR) {
        // ---------------- prep path: rows [pb*16, pb*16+16) ----------------
        SmemPrep& sp = sm.prep;
        int pb = blockIdx.x - NSCR;
        int k  = t & 63;
        int g  = t >> 6;
        int r0 = pb * 16 + g * 8;
        if (t < 16) sp.slab[t] = lab[pb * 16 + t];
        __syncthreads();

        float a1[NCLS], a2[NCLS];
#pragma unroll
        for (int c = 0; c < NCLS; c++) { a1[c] = 0.0f; a2[c] = 0.0f; }
#pragma unroll
        for (int rr = 0; rr < 8; ++rr) {
            float v  = X[(r0 + rr) * NDIM + k];
            float v2 = v * v;
            int   c  = sp.slab[g * 8 + rr];
#pragma unroll
            for (int cc = 0; cc < NCLS; cc++) {
                bool m = (cc == c);
                a1[cc] += m ? v  : 0.0f;
                a2[cc] += m ? v2 : 0.0f;
            }
        }
#pragma unroll
        for (int cc = 0; cc < NCLS; cc++) {
            sp.red1[g][cc * NDIM + k] = a1[cc];
            sp.red2[g][cc * NDIM + k] = a2[cc];
        }
        __syncthreads();
#pragma unroll
        for (int q = 0; q < 4; q++) {
            int idx = q * 128 + t;
            atomicAdd(&g_s1[idx], sp.red1[0][idx] + sp.red1[1][idx]);
            atomicAdd(&g_s2[idx], sp.red2[0][idx] + sp.red2[1][idx]);
        }
        if (t < NCLS) {
            int cnt = 0;
#pragma unroll
            for (int rr = 0; rr < 16; rr++) cnt += (sp.slab[rr] == t) ? 1 : 0;
            atomicAdd(&g_hist[t], cnt);
        }
    } else {
        // ---------------- screen path (tf32 MMA) ----------------
        SmemScreen& ss = sm.scr;
        // decode linear id -> (bi, bj), bj >= bi; counts per bi: 64 - bi
        int L = blockIdx.x;
        int bi = 0;
#pragma unroll
        for (int k = 0; k < 64; k++) {
            int cnt = 64 - k;
            bool adv = (L >= cnt);
            L  -= adv ? cnt : 0;
            bi += adv ? 1 : 0;
        }
        int bj    = bi + L;
        int ibase = bi * TT;
        int jbase = bj * TT;

        if (t == 0) ss.scnt = 0;
        {
            float4 f0 = Xv[(ibase + t) * 16 + 0];
            float4 f1 = Xv[(ibase + t) * 16 + 1];
            float v[8] = {f0.x, f0.y, f0.z, f0.w, f1.x, f1.y, f1.z, f1.w};
            float hn = 0.0f;
#pragma unroll
            for (int d = 0; d < 8; d++) {
                float fr = to_tf32(v[d]);
                ss.A[t * 9 + d] = fr;
                hn = fmaf(fr, fr, hn);
            }
            ss.hi[t] = 0.5f * hn;
        }
        {
            float4 f0 = Xv[(jbase + t) * 16 + 0];
            float4 f1 = Xv[(jbase + t) * 16 + 1];
            float v[8] = {f0.x, f0.y, f0.z, f0.w, f1.x, f1.y, f1.z, f1.w};
            float hn = 0.0f;
#pragma unroll
            for (int d = 0; d < 8; d++) {
                float fr = to_tf32(v[d]);
                ss.B[t * 9 + d] = fr;
                hn = fmaf(fr, fr, hn);
            }
            ss.hj[t] = 0.5f * hn;
        }
        __syncthreads();

        int w    = t >> 5;
        int lane = t & 31;
        int g    = lane >> 2;       // 0..7
        int q    = lane & 3;        // 0..3

        // warp w owns i-subtiles {2w, 2w+1} (m16 each) x 16 j-subtiles (n8 each)
#pragma unroll
        for (int s = 0; s < 2; ++s) {
            int mi = w * 2 + s;
            int r0 = mi * 16 + g;
            int r1 = r0 + 8;
            unsigned a0 = __float_as_uint(ss.A[r0 * 9 + q]);
            unsigned a1 = __float_as_uint(ss.A[r1 * 9 + q]);
            unsigned a2 = __float_as_uint(ss.A[r0 * 9 + q + 4]);
            unsigned a3 = __float_as_uint(ss.A[r1 * 9 + q + 4]);
            float ci0 = MARG - ss.hi[r0];
            float ci1 = MARG - ss.hi[r1];
            int row0 = ibase + r0;
            int row1 = ibase + r1;
#pragma unroll 4
            for (int nj = 0; nj < 16; ++nj) {
                unsigned b0 = __float_as_uint(ss.B[(nj * 8 + g) * 9 + q]);
                unsigned b1 = __float_as_uint(ss.B[(nj * 8 + g) * 9 + q + 4]);
                float hj0 = ss.hj[nj * 8 + 2 * q];
                float hj1 = ss.hj[nj * 8 + 2 * q + 1];
                float c0 = ci0 - hj0, c1 = ci0 - hj1;
                float c2 = ci1 - hj0, c3 = ci1 - hj1;
                asm volatile(
                    "mma.sync.aligned.m16n8k8.row.col.f32.tf32.tf32.f32 "
                    "{%0,%1,%2,%3}, {%4,%5,%6,%7}, {%8,%9}, {%0,%1,%2,%3};"
                    : "+f"(c0), "+f"(c1), "+f"(c2), "+f"(c3)
                    : "r"(a0), "r"(a1), "r"(a2), "r"(a3), "r"(b0), "r"(b1));
                bool p = (c0 > 0.0f) | (c1 > 0.0f) | (c2 > 0.0f) | (c3 > 0.0f);
                if (__any_sync(0xFFFFFFFFu, p)) {
                    int col0 = jbase + nj * 8 + 2 * q;
                    if (c0 > 0.0f) {
                        int ix = atomicAdd(&ss.scnt, 1);
                        if (ix < SCAP) ss.sbuf[ix] = ((unsigned)row0 << 13) | (unsigned)col0;
                    }
                    if (c1 > 0.0f) {
                        int ix = atomicAdd(&ss.scnt, 1);
                        if (ix < SCAP) ss.sbuf[ix] = ((unsigned)row0 << 13) | (unsigned)(col0 + 1);
                    }
                    if (c2 > 0.0f) {
                        int ix = atomicAdd(&ss.scnt, 1);
                        if (ix < SCAP) ss.sbuf[ix] = ((unsigned)row1 << 13) | (unsigned)col0;
                    }
                    if (c3 > 0.0f) {
                        int ix = atomicAdd(&ss.scnt, 1);
                        if (ix < SCAP) ss.sbuf[ix] = ((unsigned)row1 << 13) | (unsigned)(col0 + 1);
                    }
                }
            }
        }
        __syncthreads();

        if (ss.scnt <= SCAP) {
            int n = ss.scnt;
            for (int qq = t; qq < n; qq += 128) {
                unsigned e = ss.sbuf[qq];
                eval_pair(X, lab, (int)(e >> 13), (int)(e & 8191u));
            }
        } else {
            // overflow (correctness guard): scalar re-screen of this tile from smem
#pragma unroll 1
            for (int j = 0; j < TT; ++j) {
                float dot = 0.0f;
#pragma unroll
                for (int d = 0; d < 8; d++)
                    dot = fmaf(ss.A[t * 9 + d], ss.B[j * 9 + d], dot);
                if (dot > ss.hi[t] + ss.hj[j] - MARG)
                    eval_pair(X, lab, ibase + t, jbase + j);
            }
        }
    }

    // ---------------- completion ticket; last block finalizes ----------------
    __threadfence();
    __syncthreads();
    if (t == 0) {
        int v = atomicAdd(&g_done, 1);
        s_last = (v == NBLK - 1) ? 1 : 0;
    }
    __syncthreads();
    if (!s_last) return;

    double part = 0.0;
#pragma unroll
    for (int q = 0; q < 4; q++) {
        int idx = q * 128 + t;
        double S1 = (double)g_s1[idx];
        double S2 = (double)g_s2[idx];
        part += (double)g_hist[idx >> 6] * S2 - S1 * S1;
    }
#pragma unroll
    for (int s = 16; s > 0; s >>= 1)
        part += __shfl_down_sync(0xFFFFFFFFu, part, s);
    if ((t & 31) == 0) s_part[t >> 5] = part;
    __syncthreads();
    if (t == 0) {
        double pos  = 2.0 * (s_part[0] + s_part[1] + s_part[2] + s_part[3]);
        double loss = (pos + g_neg) / ((double)N_PTS * (double)(N_PTS - 1));
        out[0] = (float)loss;
    }
#pragma unroll
    for (int q = 0; q < 4; q++) {
        int idx = q * 128 + t;
        g_s1[idx] = 0.0f;
        g_s2[idx] = 0.0f;
    }
    if (t < NCLS) g_hist[t] = 0;
    if (t == 0) { g_neg = 0.0; g_done = 0; }
}

extern "C" void kernel_launch(void* const* d_in, const int* in_sizes, int n_in,
                              void* d_out, int out_size) {
    const float* X   = (const float*)d_in[0];
    const int*   lab = (const int*)d_in[1];
    float*       out = (float*)d_out;

    fused_kernel<<<NBLK, 128>>>(X, lab, out);
}